// round 2
// baseline (speedup 1.0000x reference)
#include <cuda_runtime.h>
#include <cstdint>

#define NNODES 50000
#define NEDGES 1600000
#define CHID   128

// ---------------- scratch (no allocations allowed) ----------------
__device__ float g_bufA[NNODES * CHID];
__device__ float g_bufB[NNODES * CHID];
__device__ float g_es[NNODES];
__device__ float g_ed[NNODES];
__device__ int   g_rowptr[NNODES + 1];
__device__ int   g_cursor[NNODES];
__device__ int   g_srcs[NEDGES];

__device__ __forceinline__ float lrelu(float x) { return x > 0.f ? x : 0.2f * x; }

// ---------------- CSR build ----------------
__global__ void zero_int_kernel(int* a, int n) {
    int i = blockIdx.x * blockDim.x + threadIdx.x;
    if (i < n) a[i] = 0;
}

__global__ void count_kernel(const int* __restrict__ dst, int* __restrict__ counts, int E) {
    for (int e = blockIdx.x * blockDim.x + threadIdx.x; e < E; e += gridDim.x * blockDim.x)
        atomicAdd(&counts[dst[e]], 1);
}

__global__ void scan_kernel(const int* __restrict__ counts, int* __restrict__ rowptr, int n) {
    __shared__ int sh[1024];
    int tid = threadIdx.x;
    int carry = 0;
    if (tid == 0) rowptr[0] = 0;
    for (int base = 0; base < n; base += 1024) {
        int i = base + tid;
        int v = (i < n) ? counts[i] : 0;
        sh[tid] = v;
        __syncthreads();
        for (int off = 1; off < 1024; off <<= 1) {
            int t = (tid >= off) ? sh[tid - off] : 0;
            __syncthreads();
            sh[tid] += t;
            __syncthreads();
        }
        if (i < n) rowptr[i + 1] = carry + sh[tid];
        carry += sh[1023];
        __syncthreads();
    }
}

__global__ void scatter_kernel(const int* __restrict__ src, const int* __restrict__ dst,
                               const int* __restrict__ rowptr, int* __restrict__ cursor,
                               int* __restrict__ out, int E) {
    for (int e = blockIdx.x * blockDim.x + threadIdx.x; e < E; e += gridDim.x * blockDim.x) {
        int d = dst[e];
        int pos = rowptr[d] + atomicAdd(&cursor[d], 1);
        out[pos] = src[e];
    }
}

// ---------------- GEMM: C[M,Ncol] = A[M,K] @ B[K,Ncol] (row-major) ----------------
#define BM 128
#define BN 64
#define BKK 16
#define TM 8
#define TN 4

__global__ __launch_bounds__(256) void gemm_kernel(const float* __restrict__ A,
                                                   const float* __restrict__ Bm,
                                                   float* __restrict__ Cm,
                                                   int M, int K, int Ncol) {
    __shared__ float As[BKK][BM + 4];
    __shared__ float Bs[BKK][BN];
    const int tid = threadIdx.x;
    const int block_m = blockIdx.x * BM;
    const int block_n = blockIdx.y * BN;
    const int tcol = tid & 15;   // 0..15
    const int trow = tid >> 4;   // 0..15

    float acc[TM][TN];
#pragma unroll
    for (int i = 0; i < TM; i++)
#pragma unroll
        for (int j = 0; j < TN; j++) acc[i][j] = 0.f;

    const int arow = tid >> 2;
    const int acol = (tid & 3) * 4;
    const int brow = tid >> 4;
    const int bcol = (tid & 15) * 4;

    for (int k0 = 0; k0 < K; k0 += BKK) {
#pragma unroll
        for (int r = 0; r < BM; r += 64) {
            int grow = block_m + arow + r;
            float4 v = make_float4(0.f, 0.f, 0.f, 0.f);
            if (grow < M) v = *reinterpret_cast<const float4*>(&A[(size_t)grow * K + k0 + acol]);
            As[acol + 0][arow + r] = v.x;
            As[acol + 1][arow + r] = v.y;
            As[acol + 2][arow + r] = v.z;
            As[acol + 3][arow + r] = v.w;
        }
        {
            float4 v = *reinterpret_cast<const float4*>(&Bm[(size_t)(k0 + brow) * Ncol + block_n + bcol]);
            *reinterpret_cast<float4*>(&Bs[brow][bcol]) = v;
        }
        __syncthreads();
#pragma unroll
        for (int kk = 0; kk < BKK; kk++) {
            float4 a0 = *reinterpret_cast<const float4*>(&As[kk][trow * TM]);
            float4 a1 = *reinterpret_cast<const float4*>(&As[kk][trow * TM + 4]);
            float4 b4 = *reinterpret_cast<const float4*>(&Bs[kk][tcol * TN]);
            float a[TM] = {a0.x, a0.y, a0.z, a0.w, a1.x, a1.y, a1.z, a1.w};
            float b[TN] = {b4.x, b4.y, b4.z, b4.w};
#pragma unroll
            for (int i = 0; i < TM; i++)
#pragma unroll
                for (int j = 0; j < TN; j++) acc[i][j] += a[i] * b[j];
        }
        __syncthreads();
    }
#pragma unroll
    for (int i = 0; i < TM; i++) {
        int grow = block_m + trow * TM + i;
        if (grow < M) {
            float4 v = make_float4(acc[i][0], acc[i][1], acc[i][2], acc[i][3]);
            *reinterpret_cast<float4*>(&Cm[(size_t)grow * Ncol + block_n + tcol * TN]) = v;
        }
    }
}

// ---------------- attention scalar coefficients es/ed ----------------
__global__ void attn_kernel(const float* __restrict__ h, const float* __restrict__ asv,
                            const float* __restrict__ adv, float* __restrict__ es,
                            float* __restrict__ ed, int N, int C) {
    int gw = (blockIdx.x * blockDim.x + threadIdx.x) >> 5;
    int lane = threadIdx.x & 31;
    if (gw >= N) return;
    float s = 0.f, d = 0.f;
    for (int c = lane; c < C; c += 32) {
        float v = h[(size_t)gw * C + c];
        s += v * asv[c];
        d += v * adv[c];
    }
#pragma unroll
    for (int o = 16; o; o >>= 1) {
        s += __shfl_xor_sync(0xffffffffu, s, o);
        d += __shfl_xor_sync(0xffffffffu, d, o);
    }
    if (lane == 0) { es[gw] = s; ed[gw] = d; }
}

// ---------------- edge-softmax + aggregation: one block per dst node ----------------
__global__ void agg_kernel(const float* __restrict__ h, const float* __restrict__ es,
                           const float* __restrict__ ed, const int* __restrict__ rowptr,
                           const int* __restrict__ srcs, const float* __restrict__ bias,
                           float* __restrict__ out, int C, int do_relu) {
    int d = blockIdx.x;
    int tid = threadIdx.x;
    int start = rowptr[d], end = rowptr[d + 1];
    float edv = ed[d];
    float self_l = lrelu(es[d] + edv);   // implicit self-loop edge

    // pass 1: segment max (including self-loop)
    float lmax = self_l;
    for (int e = start + tid; e < end; e += blockDim.x)
        lmax = fmaxf(lmax, lrelu(es[srcs[e]] + edv));
#pragma unroll
    for (int o = 16; o; o >>= 1)
        lmax = fmaxf(lmax, __shfl_xor_sync(0xffffffffu, lmax, o));
    __shared__ float red[4];
    if ((tid & 31) == 0) red[tid >> 5] = lmax;
    __syncthreads();
    if (tid == 0) {
        float m0 = red[0];
        int nw = blockDim.x >> 5;
        for (int w = 1; w < nw; w++) m0 = fmaxf(m0, red[w]);
        red[0] = m0;
    }
    __syncthreads();
    float m = red[0];

    // pass 2: exp weights computed once per edge into shared, then per-channel accumulate
    __shared__ float w_sh[128];
    __shared__ int   s_sh[128];
    float wself = __expf(self_l - m);
    float acc = wself * h[(size_t)d * C + tid];
    float denom = wself;
    for (int base = start; base < end; base += blockDim.x) {
        int e = base + tid;
        if (e < end) {
            int s = srcs[e];
            s_sh[tid] = s;
            w_sh[tid] = __expf(lrelu(es[s] + edv) - m);
        }
        __syncthreads();
        int cnt = min((int)blockDim.x, end - base);
        for (int j = 0; j < cnt; j++) {
            float w = w_sh[j];
            acc += w * h[(size_t)s_sh[j] * C + tid];
            denom += w;
        }
        __syncthreads();
    }
    float o = acc / denom + bias[tid];
    if (do_relu) o = fmaxf(o, 0.f);
    out[(size_t)d * C + tid] = o;
}

// ---------------- launch ----------------
extern "C" void kernel_launch(void* const* d_in, const int* in_sizes, int n_in,
                              void* d_out, int out_size) {
    const float* x   = (const float*)d_in[0];
    const int*   ei  = (const int*)  d_in[1];
    const float* W0  = (const float*)d_in[2];
    const float* as0 = (const float*)d_in[3];
    const float* ad0 = (const float*)d_in[4];
    const float* b0  = (const float*)d_in[5];
    const float* W1  = (const float*)d_in[6];
    const float* as1 = (const float*)d_in[7];
    const float* ad1 = (const float*)d_in[8];
    const float* b1  = (const float*)d_in[9];
    const float* W2  = (const float*)d_in[10];
    const float* as2 = (const float*)d_in[11];
    const float* ad2 = (const float*)d_in[12];
    const float* b2  = (const float*)d_in[13];
    float* out = (float*)d_out;

    const int N = in_sizes[0] / CHID;   // 50000
    const int E = in_sizes[1] / 2;      // 1600000
    const int* srcp = ei;
    const int* dstp = ei + E;

    float *bufA, *bufB, *es, *ed;
    int *rowptr, *cursor, *srcs;
    cudaGetSymbolAddress((void**)&bufA,   g_bufA);
    cudaGetSymbolAddress((void**)&bufB,   g_bufB);
    cudaGetSymbolAddress((void**)&es,     g_es);
    cudaGetSymbolAddress((void**)&ed,     g_ed);
    cudaGetSymbolAddress((void**)&rowptr, g_rowptr);
    cudaGetSymbolAddress((void**)&cursor, g_cursor);
    cudaGetSymbolAddress((void**)&srcs,   g_srcs);

    // CSR by destination (same for all 3 layers)
    zero_int_kernel<<<(N + 255) / 256, 256>>>(cursor, N);
    count_kernel<<<592, 256>>>(dstp, cursor, E);
    scan_kernel<<<1, 1024>>>(cursor, rowptr, N);
    zero_int_kernel<<<(N + 255) / 256, 256>>>(cursor, N);
    scatter_kernel<<<592, 256>>>(srcp, dstp, rowptr, cursor, srcs, E);

    dim3 g01((N + BM - 1) / BM, 128 / BN);
    dim3 g2 ((N + BM - 1) / BM, 64 / BN);
    int attn_blocks = (N + 7) / 8;

    // layer 0: x[N,128] @ W0 -> bufA ; aggregate -> bufB (+relu)
    gemm_kernel<<<g01, 256>>>(x, W0, bufA, N, 128, 128);
    attn_kernel<<<attn_blocks, 256>>>(bufA, as0, ad0, es, ed, N, 128);
    agg_kernel<<<N, 128>>>(bufA, es, ed, rowptr, srcs, b0, bufB, 128, 1);

    // layer 1: bufB @ W1 -> bufA ; aggregate -> bufB (+relu)
    gemm_kernel<<<g01, 256>>>(bufB, W1, bufA, N, 128, 128);
    attn_kernel<<<attn_blocks, 256>>>(bufA, as1, ad1, es, ed, N, 128);
    agg_kernel<<<N, 128>>>(bufA, es, ed, rowptr, srcs, b1, bufB, 128, 1);

    // layer 2: bufB @ W2 -> bufA[:, :64] ; aggregate -> d_out (no relu)
    gemm_kernel<<<g2, 256>>>(bufB, W2, bufA, N, 128, 64);
    attn_kernel<<<attn_blocks, 256>>>(bufA, as2, ad2, es, ed, N, 64);
    agg_kernel<<<N, 64>>>(bufA, es, ed, rowptr, srcs, b2, out, 64, 0);
}